// round 15
// baseline (speedup 1.0000x reference)
#include <cuda_runtime.h>
#include <math.h>
#include <stdint.h>

#define ND   64
#define ED   32
#define HID  256
#define MSGD 128
#define MAX_EDGES 800000
#define MAX_NODES 50000

#define BM    64      // node_proj / agent tile
#define EBM   32      // edge tile
#define HPAD  260
#define EPAD  36
#define APAD  68
#define XPAD  132
#define PROJW 512

typedef unsigned long long u64;
typedef unsigned int u32;

// ---- packed f32x2 helpers ----
__device__ __forceinline__ u64 ffma2(u64 a, u64 b, u64 c) {
    u64 d;
    asm("fma.rn.f32x2 %0, %1, %2, %3;" : "=l"(d) : "l"(a), "l"(b), "l"(c));
    return d;
}
__device__ __forceinline__ u64 pack2(float x) {
    u64 r;
    asm("mov.b64 %0, {%1, %1};" : "=l"(r) : "f"(x));
    return r;
}
__device__ __forceinline__ float2 unpack2(u64 v) {
    float2 f;
    asm("mov.b64 {%0, %1}, %2;" : "=f"(f.x), "=f"(f.y) : "l"(v));
    return f;
}
__device__ __forceinline__ void red_add_v4(float* p, float4 v) {
    asm volatile("red.global.add.v4.f32 [%0], {%1, %2, %3, %4};"
                 :: "l"(p), "f"(v.x), "f"(v.y), "f"(v.z), "f"(v.w) : "memory");
}
__device__ __forceinline__ void red_add_v2(float* p, float x, float y) {
    asm volatile("red.global.add.v2.f32 [%0], {%1, %2};"
                 :: "l"(p), "f"(x), "f"(y) : "memory");
}

// ---- bf16 helpers ----
__device__ __forceinline__ u32 pack_bf16x2(float lo, float hi) {
    u32 r;  // low 16 bits <- lo, high <- hi
    asm("cvt.rn.bf16x2.f32 %0, %1, %2;" : "=r"(r) : "f"(hi), "f"(lo));
    return r;
}
__device__ __forceinline__ float bf_lo_f(u32 p) { return __uint_as_float(p << 16); }
__device__ __forceinline__ float bf_hi_f(u32 p) { return __uint_as_float(p & 0xFFFF0000u); }

// ---- smem addr ----
__device__ __forceinline__ u32 smem_u32(const void* p) {
    u32 a;
    asm("{ .reg .u64 t; cvta.to.shared.u64 t, %1; cvt.u32.u64 %0, t; }" : "=r"(a) : "l"(p));
    return a;
}

// ---- warp MMA (HMMA fallback; plain PTX, no 'a'-gated features) ----
__device__ __forceinline__ void ldsm_x4(u32& r0, u32& r1, u32& r2, u32& r3, u32 addr) {
    asm volatile("ldmatrix.sync.aligned.m8n8.x4.shared.b16 {%0,%1,%2,%3},[%4];"
                 : "=r"(r0), "=r"(r1), "=r"(r2), "=r"(r3) : "r"(addr));
}
__device__ __forceinline__ void ldsm_x4_t(u32& r0, u32& r1, u32& r2, u32& r3, u32 addr) {
    asm volatile("ldmatrix.sync.aligned.m8n8.x4.trans.shared.b16 {%0,%1,%2,%3},[%4];"
                 : "=r"(r0), "=r"(r1), "=r"(r2), "=r"(r3) : "r"(addr));
}
__device__ __forceinline__ void mma_bf16(float* d, u32 a0, u32 a1, u32 a2, u32 a3,
                                         u32 b0, u32 b1) {
    asm volatile(
        "mma.sync.aligned.m16n8k16.row.col.f32.bf16.bf16.f32 "
        "{%0,%1,%2,%3},{%4,%5,%6,%7},{%8,%9},{%0,%1,%2,%3};"
        : "+f"(d[0]), "+f"(d[1]), "+f"(d[2]), "+f"(d[3])
        : "r"(a0), "r"(a1), "r"(a2), "r"(a3), "r"(b0), "r"(b1));
}

// ---- scratch ----
__device__ int   g_count;
__device__ int   g_active[MAX_EDGES];
__device__ int   g_crecv[MAX_EDGES];
__device__ float g_denom[MAX_NODES];
__device__ float g_aggr[(size_t)MAX_NODES * MSGD];
__device__ float g_proj[(size_t)MAX_NODES * PROJW];
__device__ unsigned short g_w2bh[HID * MSGD];   // W2 [k][n] bf16 hi
__device__ unsigned short g_w2bl[HID * MSGD];   // W2 [k][n] bf16 lo

// ---------------- init ----------------
__global__ void init_kernel(int n_agents) {
    int i = blockIdx.x * blockDim.x + threadIdx.x;
    int total = n_agents * MSGD;
    if (i < total) g_aggr[i] = 0.f;
    if (i < n_agents) g_denom[i] = 0.f;
    if (i == 0) g_count = 0;
}

// ---------------- W2 -> bf16 hi/lo images ([k][n] row-major) -----------------
__global__ void w2_img_kernel(const float* __restrict__ W2) {
    int i = blockIdx.x * blockDim.x + threadIdx.x;
    if (i >= HID * MSGD) return;
    float v = W2[i];
    u32 b = __float_as_uint(v);
    u32 hb = (b + 0x7FFFu + ((b >> 16) & 1u)) >> 16;      // RNE bf16
    float hf = __uint_as_float(hb << 16);
    float lv = v - hf;
    u32 lb32 = __float_as_uint(lv);
    u32 lb = (lb32 + 0x7FFFu + ((lb32 >> 16) & 1u)) >> 16;
    g_w2bh[i] = (unsigned short)hb;
    g_w2bl[i] = (unsigned short)lb;
}

// ---------------- compact ----------------
__global__ void compact_kernel(const int* __restrict__ recv, int n_edges, int n_agents) {
    int i = blockIdx.x * blockDim.x + threadIdx.x;
    if (i >= n_edges) return;
    int r = recv[i];
    if (r < n_agents) {
        int p = atomicAdd(&g_count, 1);
        g_active[p] = i;
        g_crecv[p]  = r;
    }
}

// ---------------- node projections ----------------
__global__ __launch_bounds__(256, 2) void node_proj_kernel(
    const float* __restrict__ node_feats, const float* __restrict__ W1,
    int n_nodes, int n_agents)
{
    __shared__ float s_a[BM][APAD];
    const int r0 = blockIdx.x * BM;
    const int by = blockIdx.y;
    const int lim = (by == 0) ? n_nodes : n_agents;
    if (r0 >= lim) return;
    const int tid = threadIdx.x;

    for (int idx = tid; idx < BM * 16; idx += 256) {
        int m = idx >> 4, p = idx & 15;
        int row = r0 + m;
        float4 v = make_float4(0.f, 0.f, 0.f, 0.f);
        if (row < lim) v = ((const float4*)(node_feats + (size_t)row * ND))[p];
        *(float4*)&s_a[m][p * 4] = v;
    }
    __syncthreads();

    const int tx = tid & 31, ty = tid >> 5;
    const int n0 = tx * 8, m0 = ty * 8;
    const float* Wblk = W1 + (size_t)(by * 64) * HID;

    u64 acc[8][4];
    #pragma unroll
    for (int i = 0; i < 8; i++)
        #pragma unroll
        for (int p = 0; p < 4; p++) acc[i][p] = 0ull;

    for (int k = 0; k < 64; k += 4) {
        float av[8][4];
        #pragma unroll
        for (int i = 0; i < 8; i++)
            *(float4*)av[i] = *(const float4*)&s_a[m0 + i][k];
        #pragma unroll
        for (int kk = 0; kk < 4; kk++) {
            const ulonglong2* wp = (const ulonglong2*)(Wblk + (k + kk) * HID + n0);
            ulonglong2 w01 = wp[0], w23 = wp[1];
            u64 w[4] = {w01.x, w01.y, w23.x, w23.y};
            #pragma unroll
            for (int i = 0; i < 8; i++) {
                u64 a = pack2(av[i][kk]);
                #pragma unroll
                for (int p = 0; p < 4; p++) acc[i][p] = ffma2(a, w[p], acc[i][p]);
            }
        }
    }
    #pragma unroll
    for (int i = 0; i < 8; i++) {
        int row = r0 + m0 + i;
        if (row < lim) {
            float* dst = g_proj + (size_t)row * PROJW + by * 256 + n0;
            #pragma unroll
            for (int g = 0; g < 2; g++) {
                float2 u0 = unpack2(acc[i][2 * g]);
                float2 u1 = unpack2(acc[i][2 * g + 1]);
                *(float4*)(dst + g * 4) = make_float4(u0.x, u0.y, u1.x, u1.y);
            }
        }
    }
}

// ---------------- edge kernel smem layout (bytes) ----------------
#define SM_IDX  0                         // 3*32 ints
#define SM_GP   384                       // 4*32 floats
#define SM_B2   896                       // 128 floats
#define SM_WG   1408                      // 128 floats
#define SM_E    1920                      // 32*36 floats
#define SM_H    6528                      // 32*260 floats
#define SM_AHI  39808                     // 32 rows * 528 B (bf16, padded)
#define SM_ALO  56704
#define SM_BHI  73600                     // 256 rows * 272 B (bf16, padded)
#define SM_BLO  143232
#define SM_TOT  212864
#define ASTB 528
#define BSTB 272

// ---------------- persistent fused edge MLP: FFMA2 GEMM1 + HMMA GEMM2 --------
__global__ __launch_bounds__(256) void edge_mlp_kernel(
    const float* __restrict__ edge_feats,
    const float* __restrict__ W1, const float* __restrict__ b1,
    const float* __restrict__ b2,
    const float* __restrict__ w_gate, const float* __restrict__ b_gate,
    const int* __restrict__ senders)
{
    extern __shared__ char smem[];
    const u32 sb = smem_u32(smem);
    int*   s_is   = (int*)(smem + SM_IDX);
    int*   s_ir   = s_is + EBM;
    int*   s_eidx = s_ir + EBM;
    float* s_gp   = (float*)(smem + SM_GP);
    float* s_b2   = (float*)(smem + SM_B2);
    float* s_wg   = (float*)(smem + SM_WG);
    float (*s_e)[EPAD] = (float (*)[EPAD])(smem + SM_E);
    float (*s_h)[HPAD] = (float (*)[HPAD])(smem + SM_H);

    const int cnt = g_count;
    const int tid = threadIdx.x;
    const int wid = tid >> 5, lane = tid & 31;
    const float bg = b_gate[0];

    // ---- one-time staging: b2, w_gate, W2 bf16 hi/lo images (padded rows) ----
    if (tid < 128) { s_b2[tid] = b2[tid]; s_wg[tid] = w_gate[tid]; }
    {
        const uint4* srcH = (const uint4*)g_w2bh;   // 4096 uint4 (row-major 256x128 bf16)
        const uint4* srcL = (const uint4*)g_w2bl;
        for (int i = tid; i < 4096; i += 256) {
            int row = i >> 4, q = i & 15;
            *(uint4*)(smem + SM_BHI + row * BSTB + q * 16) = srcH[i];
            *(uint4*)(smem + SM_BLO + row * BSTB + q * 16) = srcL[i];
        }
    }

    // GEMM1 mapping: warp=rows ty*4..+3, lane=cols tx*8..+7
    const int tx = lane, ty = wid;
    const int m0 = ty * 4, n0 = tx * 8;
    // MMA mapping: warp slab rows rw0..rw0+15, cols cw0..cw0+31
    const int rw0 = (wid & 1) * 16;
    const int cw0 = (wid >> 1) * 32;
    const u32 aOffHi = sb + SM_AHI + (u32)(rw0 + (lane & 15)) * ASTB + ((lane >> 4) << 4);
    const u32 aOffLo = aOffHi + (SM_ALO - SM_AHI);
    const u32 bRowOff = (u32)(lane & 15) * BSTB + (u32)((cw0 + ((lane >> 4) << 3)) * 2);
    const u32 bOffHi = sb + SM_BHI + bRowOff;
    const u32 bOffLo = sb + SM_BLO + bRowOff;
    const int group = lane >> 2, tg = lane & 3;
    const int cg = wid >> 1;

    const float* W1e = W1 + (size_t)(2 * ND) * HID;

    for (int e0 = blockIdx.x * EBM; e0 < cnt; e0 += gridDim.x * EBM) {
        __syncthreads();   // smem safe to reuse (covers staging on first iter)
        if (tid < EBM) {
            int ci = e0 + tid;
            int e = 0, s = 0, r = 0;
            if (ci < cnt) { e = g_active[ci]; s = senders[e]; r = g_crecv[ci]; }
            s_eidx[tid] = e; s_is[tid] = s; s_ir[tid] = r;
        }
        __syncthreads();

        // presum Ps+Pr (coalesced) + edge feats
        for (int idx = tid; idx < EBM * 64; idx += 256) {
            int m = idx >> 6, p = idx & 63;
            const float4 a = *(const float4*)(g_proj + (size_t)s_is[m] * PROJW + p * 4);
            const float4 b = *(const float4*)(g_proj + (size_t)s_ir[m] * PROJW + 256 + p * 4);
            *(float4*)&s_h[m][p * 4] = make_float4(a.x + b.x, a.y + b.y, a.z + b.z, a.w + b.w);
        }
        {
            int m = tid >> 3, p = tid & 7;   // 256 == EBM*8
            float4 v = make_float4(0.f, 0.f, 0.f, 0.f);
            if (e0 + m < cnt) v = ((const float4*)(edge_feats + (size_t)s_eidx[m] * ED))[p];
            *(float4*)&s_e[m][p * 4] = v;
        }
        __syncthreads();

        // ---- GEMM1 (K=32) + bias, FFMA2, 4x8 per thread ----
        u64 acc[4][4];
        {
            const u64* bp = (const u64*)(b1 + n0);
            u64 bv[4] = {bp[0], bp[1], bp[2], bp[3]};
            #pragma unroll
            for (int i = 0; i < 4; i++)
                #pragma unroll
                for (int p = 0; p < 4; p++) acc[i][p] = bv[p];
        }
        for (int k = 0; k < ED; k += 4) {
            float av[4][4];
            #pragma unroll
            for (int i = 0; i < 4; i++)
                *(float4*)av[i] = *(const float4*)&s_e[m0 + i][k];
            #pragma unroll
            for (int kk = 0; kk < 4; kk++) {
                const ulonglong2* wp = (const ulonglong2*)(W1e + (k + kk) * HID + n0);
                ulonglong2 w01 = wp[0], w23 = wp[1];
                u64 w[4] = {w01.x, w01.y, w23.x, w23.y};
                #pragma unroll
                for (int i = 0; i < 4; i++) {
                    u64 a = pack2(av[i][kk]);
                    #pragma unroll
                    for (int p = 0; p < 4; p++) acc[i][p] = ffma2(a, w[p], acc[i][p]);
                }
            }
        }

        // ---- h = relu(acc + presum) -> bf16 hi/lo A images ----
        #pragma unroll
        for (int i = 0; i < 4; i++) {
            int m = m0 + i;
            float4 hv0 = *(float4*)&s_h[m][n0];
            float4 hv1 = *(float4*)&s_h[m][n0 + 4];
            float2 u0 = unpack2(acc[i][0]), u1 = unpack2(acc[i][1]);
            float2 u2 = unpack2(acc[i][2]), u3 = unpack2(acc[i][3]);
            float h0 = fmaxf(u0.x + hv0.x, 0.f), h1 = fmaxf(u0.y + hv0.y, 0.f);
            float h2 = fmaxf(u1.x + hv0.z, 0.f), h3 = fmaxf(u1.y + hv0.w, 0.f);
            float h4 = fmaxf(u2.x + hv1.x, 0.f), h5 = fmaxf(u2.y + hv1.y, 0.f);
            float h6 = fmaxf(u3.x + hv1.z, 0.f), h7 = fmaxf(u3.y + hv1.w, 0.f);

            u32 ph0 = pack_bf16x2(h0, h1), ph1 = pack_bf16x2(h2, h3);
            u32 ph2 = pack_bf16x2(h4, h5), ph3 = pack_bf16x2(h6, h7);
            u32 pl0 = pack_bf16x2(h0 - bf_lo_f(ph0), h1 - bf_hi_f(ph0));
            u32 pl1 = pack_bf16x2(h2 - bf_lo_f(ph1), h3 - bf_hi_f(ph1));
            u32 pl2 = pack_bf16x2(h4 - bf_lo_f(ph2), h5 - bf_hi_f(ph2));
            u32 pl3 = pack_bf16x2(h6 - bf_lo_f(ph3), h7 - bf_hi_f(ph3));

            u32 off = (u32)m * ASTB + (u32)(n0 * 2);
            *(uint4*)(smem + SM_AHI + off) = make_uint4(ph0, ph1, ph2, ph3);
            *(uint4*)(smem + SM_ALO + off) = make_uint4(pl0, pl1, pl2, pl3);
        }
        __syncthreads();

        // ---- GEMM2 via mma.sync bf16: D = Ah*Bh + Al*Bh + Ah*Bl -------------
        float d[4][4];
        #pragma unroll
        for (int t = 0; t < 4; t++)
            #pragma unroll
            for (int j = 0; j < 4; j++) d[t][j] = 0.f;

        #pragma unroll 1
        for (int pass = 0; pass < 3; pass++) {
            u32 aB = (pass == 1) ? aOffLo : aOffHi;
            u32 bB = (pass == 2) ? bOffLo : bOffHi;
            #pragma unroll 4
            for (int k = 0; k < HID; k += 16) {
                u32 a0, a1, a2, a3;
                ldsm_x4(a0, a1, a2, a3, aB + (u32)(k * 2));
                u32 b0, b1, b2r, b3, b4, b5, b6, b7;
                ldsm_x4_t(b0, b1, b2r, b3, bB + (u32)(k * BSTB));
                ldsm_x4_t(b4, b5, b6, b7, bB + (u32)(k * BSTB) + 32);
                mma_bf16(d[0], a0, a1, a2, a3, b0, b1);
                mma_bf16(d[1], a0, a1, a2, a3, b2r, b3);
                mma_bf16(d[2], a0, a1, a2, a3, b4, b5);
                mma_bf16(d[3], a0, a1, a2, a3, b6, b7);
            }
        }

        // ---- epilogue: relu + gate partials + exp + scatter -----------------
        const int row1 = rw0 + group, row2 = row1 + 8;
        float v1[8], v2[8];
        float p1 = 0.f, p2 = 0.f;
        #pragma unroll
        for (int t = 0; t < 4; t++) {
            int c = cw0 + t * 8 + 2 * tg;
            float bb0 = s_b2[c], bb1 = s_b2[c + 1];
            float wg0 = s_wg[c], wg1 = s_wg[c + 1];
            float a0 = fmaxf(d[t][0] + bb0, 0.f), a1 = fmaxf(d[t][1] + bb1, 0.f);
            float a2 = fmaxf(d[t][2] + bb0, 0.f), a3 = fmaxf(d[t][3] + bb1, 0.f);
            v1[2 * t] = a0; v1[2 * t + 1] = a1;
            v2[2 * t] = a2; v2[2 * t + 1] = a3;
            p1 = fmaf(a0, wg0, fmaf(a1, wg1, p1));
            p2 = fmaf(a2, wg0, fmaf(a3, wg1, p2));
        }
        p1 += __shfl_xor_sync(0xffffffffu, p1, 1);
        p1 += __shfl_xor_sync(0xffffffffu, p1, 2);
        p2 += __shfl_xor_sync(0xffffffffu, p2, 1);
        p2 += __shfl_xor_sync(0xffffffffu, p2, 2);
        if (tg == 0) {
            s_gp[cg * 32 + row1] = p1;
            s_gp[cg * 32 + row2] = p2;
        }
        __syncthreads();

        if (e0 + row1 < cnt) {
            float tot = s_gp[row1] + s_gp[32 + row1] + s_gp[64 + row1] + s_gp[96 + row1];
            float ev = expf(tot + bg);
            int r = s_ir[row1];
            if (cg == 0 && tg == 0) atomicAdd(g_denom + r, ev);
            float* dst = g_aggr + (size_t)r * MSGD;
            #pragma unroll
            for (int t = 0; t < 4; t++)
                red_add_v2(dst + cw0 + t * 8 + 2 * tg, ev * v1[2 * t], ev * v1[2 * t + 1]);
        }
        if (e0 + row2 < cnt) {
            float tot = s_gp[row2] + s_gp[32 + row2] + s_gp[64 + row2] + s_gp[96 + row2];
            float ev = expf(tot + bg);
            int r = s_ir[row2];
            if (cg == 0 && tg == 0) atomicAdd(g_denom + r, ev);
            float* dst = g_aggr + (size_t)r * MSGD;
            #pragma unroll
            for (int t = 0; t < 4; t++)
                red_add_v2(dst + cw0 + t * 8 + 2 * tg, ev * v2[2 * t], ev * v2[2 * t + 1]);
        }
    }
}

// ---------------- agent MLP (divides by denom on load) -----------------------
__global__ __launch_bounds__(256, 2) void agent_mlp_kernel(
    const float* __restrict__ W_h1, const float* __restrict__ b_h1,
    const float* __restrict__ W_h2, const float* __restrict__ b_h2,
    const float* __restrict__ W_out, const float* __restrict__ b_out,
    float* __restrict__ out, int n_agents)
{
    extern __shared__ float smemf[];
    float (*s_x)[XPAD] = (float (*)[XPAD])smemf;
    float (*s_h)[HPAD] = (float (*)[HPAD])(smemf + BM * XPAD);

    const int r0 = blockIdx.x * BM;
    const int tid = threadIdx.x;

    for (int idx = tid; idx < BM * 32; idx += 256) {
        int m = idx >> 5, p = idx & 31;
        int r = r0 + m;
        float4 v = make_float4(0.f, 0.f, 0.f, 0.f);
        if (r < n_agents) {
            float inv = __frcp_rn(g_denom[r] + 1e-9f);
            v = *(const float4*)(g_aggr + (size_t)r * MSGD + p * 4);
            v.x *= inv; v.y *= inv; v.z *= inv; v.w *= inv;
        }
        *(float4*)&s_x[m][p * 4] = v;
    }
    __syncthreads();

    const int tx = tid & 31, ty = tid >> 5;
    const int n0 = tx * 8, m0 = ty * 8;

    u64 acc[8][4];
    {
        const u64* bp = (const u64*)(b_h1 + n0);
        u64 bv[4] = {bp[0], bp[1], bp[2], bp[3]};
        #pragma unroll
        for (int i = 0; i < 8; i++)
            #pragma unroll
            for (int p = 0; p < 4; p++) acc[i][p] = bv[p];
    }
    for (int k = 0; k < MSGD; k += 4) {
        float av[8][4];
        #pragma unroll
        for (int i = 0; i < 8; i++)
            *(float4*)av[i] = *(const float4*)&s_x[m0 + i][k];
        #pragma unroll
        for (int kk = 0; kk < 4; kk++) {
            const ulonglong2* wp = (const ulonglong2*)(W_h1 + (k + kk) * HID + n0);
            ulonglong2 w01 = wp[0], w23 = wp[1];
            u64 w[4] = {w01.x, w01.y, w23.x, w23.y};
            #pragma unroll
            for (int i = 0; i < 8; i++) {
                u64 a = pack2(av[i][kk]);
                #pragma unroll
                for (int p = 0; p < 4; p++) acc[i][p] = ffma2(a, w[p], acc[i][p]);
            }
        }
    }
    #pragma unroll
    for (int i = 0; i < 8; i++) {
        #pragma unroll
        for (int g = 0; g < 2; g++) {
            float2 u0 = unpack2(acc[i][2 * g]);
            float2 u1 = unpack2(acc[i][2 * g + 1]);
            float4 r;
            r.x = fmaxf(u0.x, 0.f); r.y = fmaxf(u0.y, 0.f);
            r.z = fmaxf(u1.x, 0.f); r.w = fmaxf(u1.y, 0.f);
            *(float4*)&s_h[m0 + i][n0 + g * 4] = r;
        }
    }
    __syncthreads();

    {
        const u64* bp = (const u64*)(b_h2 + n0);
        u64 bv[4] = {bp[0], bp[1], bp[2], bp[3]};
        #pragma unroll
        for (int i = 0; i < 8; i++)
            #pragma unroll
            for (int p = 0; p < 4; p++) acc[i][p] = bv[p];
    }
    #pragma unroll 2
    for (int k = 0; k < HID; k += 4) {
        float av[8][4];
        #pragma unroll
        for (int i = 0; i < 8; i++)
            *(float4*)av[i] = *(const float4*)&s_h[m0 + i][k];
        #pragma unroll
        for (int kk = 0; kk < 4; kk++) {
            const ulonglong2* wp = (const ulonglong2*)(W_h2 + (k + kk) * HID + n0);
            ulonglong2 w01 = wp[0], w23 = wp[1];
            u64 w[4] = {w01.x, w01.y, w23.x, w23.y};
            #pragma unroll
            for (int i = 0; i < 8; i++) {
                u64 a = pack2(av[i][kk]);
                #pragma unroll
                for (int p = 0; p < 4; p++) acc[i][p] = ffma2(a, w[p], acc[i][p]);
            }
        }
    }

    float wo[8];
    *(float4*)&wo[0] = *(const float4*)(W_out + n0);
    *(float4*)&wo[4] = *(const float4*)(W_out + n0 + 4);
    float partial[8];
    #pragma unroll
    for (int i = 0; i < 8; i++) {
        float s = 0.f;
        #pragma unroll
        for (int p = 0; p < 4; p++) {
            float2 u = unpack2(acc[i][p]);
            s = fmaf(fmaxf(u.x, 0.f), wo[2 * p], s);
            s = fmaf(fmaxf(u.y, 0.f), wo[2 * p + 1], s);
        }
        partial[i] = s;
    }
    #pragma unroll
    for (int o = 16; o >= 1; o >>= 1) {
        #pragma unroll
        for (int i = 0; i < 8; i++)
            partial[i] += __shfl_xor_sync(0xffffffffu, partial[i], o);
    }
    if (tx == 0) {
        float bo = b_out[0];
        #pragma unroll
        for (int i = 0; i < 8; i++) {
            int r = r0 + m0 + i;
            if (r < n_agents) out[r] = tanhf(partial[i] + bo);
        }
    }
}

// ---------------------------------------------------------------------------
extern "C" void kernel_launch(void* const* d_in, const int* in_sizes, int n_in,
                              void* d_out, int out_size) {
    const float* node_feats = (const float*)d_in[0];
    const float* edge_feats = (const float*)d_in[1];
    const float* W_msg1 = (const float*)d_in[2];
    const float* b_msg1 = (const float*)d_in[3];
    const float* W_msg2 = (const float*)d_in[4];
    const float* b_msg2 = (const float*)d_in[5];
    const float* w_gate = (const float*)d_in[6];
    const float* b_gate = (const float*)d_in[7];
    const float* W_h1   = (const float*)d_in[8];
    const float* b_h1   = (const float*)d_in[9];
    const float* W_h2   = (const float*)d_in[10];
    const float* b_h2   = (const float*)d_in[11];
    const float* W_out  = (const float*)d_in[12];
    const float* b_out  = (const float*)d_in[13];
    const int* senders   = (const int*)d_in[14];
    const int* receivers = (const int*)d_in[15];
    float* out = (float*)d_out;

    const int n_edges  = in_sizes[14];
    const int n_nodes  = in_sizes[0] / ND;
    const int n_agents = out_size;

    const int SMEM_AGENT = (BM * XPAD + BM * HPAD) * (int)sizeof(float);
    cudaFuncSetAttribute(edge_mlp_kernel, cudaFuncAttributeMaxDynamicSharedMemorySize, SM_TOT);
    cudaFuncSetAttribute(agent_mlp_kernel, cudaFuncAttributeMaxDynamicSharedMemorySize, SMEM_AGENT);

    {
        int total = n_agents * MSGD;
        init_kernel<<<(total + 255) / 256, 256>>>(n_agents);
    }
    w2_img_kernel<<<(HID * MSGD + 255) / 256, 256>>>(W_msg2);
    compact_kernel<<<(n_edges + 255) / 256, 256>>>(receivers, n_edges, n_agents);
    {
        dim3 grid((n_nodes + BM - 1) / BM, 2);
        node_proj_kernel<<<grid, 256>>>(node_feats, W_msg1, n_nodes, n_agents);
    }
    edge_mlp_kernel<<<148, 256, SM_TOT>>>(
        edge_feats, W_msg1, b_msg1, b_msg2, w_gate, b_gate, senders);
    agent_mlp_kernel<<<(n_agents + BM - 1) / BM, 256, SMEM_AGENT>>>(
        W_h1, b_h1, W_h2, b_h2, W_out, b_out, out, n_agents);
}

// round 16
// speedup vs baseline: 1.4896x; 1.4896x over previous
#include <cuda_runtime.h>
#include <math.h>
#include <stdint.h>

#define ND   64
#define ED   32
#define HID  256
#define MSGD 128
#define MAX_EDGES 800000
#define MAX_NODES 50000

#define BM    64      // node_proj / agent tile
#define EBM   64      // edge tile
#define HPAD  260
#define EPAD  36
#define APAD  68
#define XPAD  132
#define PROJW 512

typedef unsigned long long u64;
typedef unsigned int u32;

// ---- packed f32x2 helpers ----
__device__ __forceinline__ u64 ffma2(u64 a, u64 b, u64 c) {
    u64 d;
    asm("fma.rn.f32x2 %0, %1, %2, %3;" : "=l"(d) : "l"(a), "l"(b), "l"(c));
    return d;
}
__device__ __forceinline__ u64 pack2(float x) {
    u64 r;
    asm("mov.b64 %0, {%1, %1};" : "=l"(r) : "f"(x));
    return r;
}
__device__ __forceinline__ float2 unpack2(u64 v) {
    float2 f;
    asm("mov.b64 {%0, %1}, %2;" : "=f"(f.x), "=f"(f.y) : "l"(v));
    return f;
}
__device__ __forceinline__ void red_add_v2(float* p, float x, float y) {
    asm volatile("red.global.add.v2.f32 [%0], {%1, %2};"
                 :: "l"(p), "f"(x), "f"(y) : "memory");
}

// ---- bf16 helpers ----
__device__ __forceinline__ u32 pack_bf16x2(float lo, float hi) {
    u32 r;
    asm("cvt.rn.bf16x2.f32 %0, %1, %2;" : "=r"(r) : "f"(hi), "f"(lo));
    return r;
}
__device__ __forceinline__ float bf_lo_f(u32 p) { return __uint_as_float(p << 16); }
__device__ __forceinline__ float bf_hi_f(u32 p) { return __uint_as_float(p & 0xFFFF0000u); }

__device__ __forceinline__ u32 smem_u32(const void* p) {
    u32 a;
    asm("{ .reg .u64 t; cvta.to.shared.u64 t, %1; cvt.u32.u64 %0, t; }" : "=r"(a) : "l"(p));
    return a;
}

// ---- warp MMA (plain PTX HMMA path, no arch-'a' features) ----
__device__ __forceinline__ void ldsm_x4(u32& r0, u32& r1, u32& r2, u32& r3, u32 addr) {
    asm volatile("ldmatrix.sync.aligned.m8n8.x4.shared.b16 {%0,%1,%2,%3},[%4];"
                 : "=r"(r0), "=r"(r1), "=r"(r2), "=r"(r3) : "r"(addr));
}
__device__ __forceinline__ void ldsm_x4_t(u32& r0, u32& r1, u32& r2, u32& r3, u32 addr) {
    asm volatile("ldmatrix.sync.aligned.m8n8.x4.trans.shared.b16 {%0,%1,%2,%3},[%4];"
                 : "=r"(r0), "=r"(r1), "=r"(r2), "=r"(r3) : "r"(addr));
}
__device__ __forceinline__ void mma_bf16(float* d, u32 a0, u32 a1, u32 a2, u32 a3,
                                         u32 b0, u32 b1) {
    asm volatile(
        "mma.sync.aligned.m16n8k16.row.col.f32.bf16.bf16.f32 "
        "{%0,%1,%2,%3},{%4,%5,%6,%7},{%8,%9},{%0,%1,%2,%3};"
        : "+f"(d[0]), "+f"(d[1]), "+f"(d[2]), "+f"(d[3])
        : "r"(a0), "r"(a1), "r"(a2), "r"(a3), "r"(b0), "r"(b1));
}

// ---- scratch ----
__device__ int   g_count;
__device__ int   g_active[MAX_EDGES];
__device__ int   g_crecv[MAX_EDGES];
__device__ float g_denom[MAX_NODES];
__device__ float g_aggr[(size_t)MAX_NODES * MSGD];
__device__ float g_proj[(size_t)MAX_NODES * PROJW];
__device__ unsigned short g_w2bh[HID * MSGD];   // W2 [k][n] bf16 hi
__device__ unsigned short g_w2bl[HID * MSGD];   // W2 [k][n] bf16 lo

// ---------------- init ----------------
__global__ void init_kernel(int n_agents) {
    int i = blockIdx.x * blockDim.x + threadIdx.x;
    int total = n_agents * MSGD;
    if (i < total) g_aggr[i] = 0.f;
    if (i < n_agents) g_denom[i] = 0.f;
    if (i == 0) g_count = 0;
}

// ---------------- W2 -> bf16 hi/lo images ----------------
__global__ void w2_img_kernel(const float* __restrict__ W2) {
    int i = blockIdx.x * blockDim.x + threadIdx.x;
    if (i >= HID * MSGD) return;
    float v = W2[i];
    u32 b = __float_as_uint(v);
    u32 hb = (b + 0x7FFFu + ((b >> 16) & 1u)) >> 16;      // RNE bf16
    float hf = __uint_as_float(hb << 16);
    float lv = v - hf;
    u32 lb32 = __float_as_uint(lv);
    u32 lb = (lb32 + 0x7FFFu + ((lb32 >> 16) & 1u)) >> 16;
    g_w2bh[i] = (unsigned short)hb;
    g_w2bl[i] = (unsigned short)lb;
}

// ---------------- compact ----------------
__global__ void compact_kernel(const int* __restrict__ recv, int n_edges, int n_agents) {
    int i = blockIdx.x * blockDim.x + threadIdx.x;
    if (i >= n_edges) return;
    int r = recv[i];
    if (r < n_agents) {
        int p = atomicAdd(&g_count, 1);
        g_active[p] = i;
        g_crecv[p]  = r;
    }
}

// ---------------- node projections ----------------
__global__ __launch_bounds__(256, 2) void node_proj_kernel(
    const float* __restrict__ node_feats, const float* __restrict__ W1,
    int n_nodes, int n_agents)
{
    __shared__ float s_a[BM][APAD];
    const int r0 = blockIdx.x * BM;
    const int by = blockIdx.y;
    const int lim = (by == 0) ? n_nodes : n_agents;
    if (r0 >= lim) return;
    const int tid = threadIdx.x;

    for (int idx = tid; idx < BM * 16; idx += 256) {
        int m = idx >> 4, p = idx & 15;
        int row = r0 + m;
        float4 v = make_float4(0.f, 0.f, 0.f, 0.f);
        if (row < lim) v = ((const float4*)(node_feats + (size_t)row * ND))[p];
        *(float4*)&s_a[m][p * 4] = v;
    }
    __syncthreads();

    const int tx = tid & 31, ty = tid >> 5;
    const int n0 = tx * 8, m0 = ty * 8;
    const float* Wblk = W1 + (size_t)(by * 64) * HID;

    u64 acc[8][4];
    #pragma unroll
    for (int i = 0; i < 8; i++)
        #pragma unroll
        for (int p = 0; p < 4; p++) acc[i][p] = 0ull;

    for (int k = 0; k < 64; k += 4) {
        float av[8][4];
        #pragma unroll
        for (int i = 0; i < 8; i++)
            *(float4*)av[i] = *(const float4*)&s_a[m0 + i][k];
        #pragma unroll
        for (int kk = 0; kk < 4; kk++) {
            const ulonglong2* wp = (const ulonglong2*)(Wblk + (k + kk) * HID + n0);
            ulonglong2 w01 = wp[0], w23 = wp[1];
            u64 w[4] = {w01.x, w01.y, w23.x, w23.y};
            #pragma unroll
            for (int i = 0; i < 8; i++) {
                u64 a = pack2(av[i][kk]);
                #pragma unroll
                for (int p = 0; p < 4; p++) acc[i][p] = ffma2(a, w[p], acc[i][p]);
            }
        }
    }
    #pragma unroll
    for (int i = 0; i < 8; i++) {
        int row = r0 + m0 + i;
        if (row < lim) {
            float* dst = g_proj + (size_t)row * PROJW + by * 256 + n0;
            #pragma unroll
            for (int g = 0; g < 2; g++) {
                float2 u0 = unpack2(acc[i][2 * g]);
                float2 u1 = unpack2(acc[i][2 * g + 1]);
                *(float4*)(dst + g * 4) = make_float4(u0.x, u0.y, u1.x, u1.y);
            }
        }
    }
}

// ---------------- edge kernel smem layout (bytes) ----------------
#define SM_IDX  0                         // 3*64 ints -> 768
#define SM_GP   768                       // 4*64 floats -> 1792
#define SM_B2   1792                      // 128 floats -> 2304
#define SM_WG   2304                      // 128 floats -> 2816
#define SM_E    2816                      // 64*36 floats -> 12032
#define SM_AHI  12032                     // 64 rows * 528 B
#define SM_ALO  45824
#define SM_BHI  79616                     // 256 rows * 272 B
#define SM_BLO  149248
#define SM_TOT  218880
#define ASTB 528
#define BSTB 272

// ---------------- persistent fused edge MLP: FFMA2 GEMM1 + HMMA GEMM2 --------
// 512 threads = 16 warps; tile = 64 edges; grid = 148 (1 block/SM persistent)
__global__ __launch_bounds__(512) void edge_mlp_kernel(
    const float* __restrict__ edge_feats,
    const float* __restrict__ W1, const float* __restrict__ b1,
    const float* __restrict__ b2,
    const float* __restrict__ w_gate, const float* __restrict__ b_gate,
    const int* __restrict__ senders)
{
    extern __shared__ char smem[];
    const u32 sb = smem_u32(smem);
    int*   s_is   = (int*)(smem + SM_IDX);
    int*   s_ir   = s_is + EBM;
    int*   s_eidx = s_ir + EBM;
    float* s_gp   = (float*)(smem + SM_GP);
    float* s_b2   = (float*)(smem + SM_B2);
    float* s_wg   = (float*)(smem + SM_WG);
    float (*s_e)[EPAD] = (float (*)[EPAD])(smem + SM_E);

    const int cnt = g_count;
    const int tid = threadIdx.x;
    const int wid = tid >> 5, lane = tid & 31;
    const float bg = b_gate[0];

    // ---- one-time staging: b2, w_gate, W2 bf16 hi/lo (padded rows) ----
    if (tid < 128) { s_b2[tid] = b2[tid]; s_wg[tid] = w_gate[tid]; }
    {
        const uint4* srcH = (const uint4*)g_w2bh;
        const uint4* srcL = (const uint4*)g_w2bl;
        for (int i = tid; i < 4096; i += 512) {
            int row = i >> 4, q = i & 15;
            *(uint4*)(smem + SM_BHI + row * BSTB + q * 16) = srcH[i];
            *(uint4*)(smem + SM_BLO + row * BSTB + q * 16) = srcL[i];
        }
    }

    // GEMM1 mapping: warp = 4 rows, lane = 8 cols
    const int m0 = wid * 4, n0 = lane * 8;
    // MMA mapping: one 16x32 slab per warp
    const int rw0 = (wid & 3) * 16;
    const int cw0 = (wid >> 2) * 32;
    const u32 aOffHi = sb + SM_AHI + (u32)(rw0 + (lane & 15)) * ASTB + ((lane >> 4) << 4);
    const u32 aOffLo = aOffHi + (SM_ALO - SM_AHI);
    const u32 bRowOff = (u32)(lane & 15) * BSTB + (u32)((cw0 + ((lane >> 4) << 3)) * 2);
    const u32 bOffHi = sb + SM_BHI + bRowOff;
    const u32 bOffLo = sb + SM_BLO + bRowOff;
    const int group = lane >> 2, tg = lane & 3;
    const int cg = wid >> 2;

    const float* W1e = W1 + (size_t)(2 * ND) * HID;

    for (int e0 = blockIdx.x * EBM; e0 < cnt; e0 += gridDim.x * EBM) {
        __syncthreads();   // smem reuse guard (covers one-time staging on iter 0)
        if (tid < EBM) {
            int ci = e0 + tid;
            int e = 0, s = 0, r = 0;
            if (ci < cnt) { e = g_active[ci]; s = senders[e]; r = g_crecv[ci]; }
            s_eidx[tid] = e; s_is[tid] = s; s_ir[tid] = r;
        }
        __syncthreads();

        // stage edge feats: 64 edges x 8 float4 == 512 threads
        {
            int m = tid >> 3, p = tid & 7;
            float4 v = make_float4(0.f, 0.f, 0.f, 0.f);
            if (e0 + m < cnt) v = ((const float4*)(edge_feats + (size_t)s_eidx[m] * ED))[p];
            *(float4*)&s_e[m][p * 4] = v;
        }
        __syncthreads();

        // ---- GEMM1 (K=32) + bias, FFMA2, 4 rows x 8 cols per thread ----
        u64 acc[4][4];
        {
            const u64* bp = (const u64*)(b1 + n0);
            u64 bv[4] = {bp[0], bp[1], bp[2], bp[3]};
            #pragma unroll
            for (int i = 0; i < 4; i++)
                #pragma unroll
                for (int p = 0; p < 4; p++) acc[i][p] = bv[p];
        }
        for (int k = 0; k < ED; k += 4) {
            float av[4][4];
            #pragma unroll
            for (int i = 0; i < 4; i++)
                *(float4*)av[i] = *(const float4*)&s_e[m0 + i][k];
            #pragma unroll
            for (int kk = 0; kk < 4; kk++) {
                const ulonglong2* wp = (const ulonglong2*)(W1e + (k + kk) * HID + n0);
                ulonglong2 w01 = wp[0], w23 = wp[1];
                u64 w[4] = {w01.x, w01.y, w23.x, w23.y};
                #pragma unroll
                for (int i = 0; i < 4; i++) {
                    u64 a = pack2(av[i][kk]);
                    #pragma unroll
                    for (int p = 0; p < 4; p++) acc[i][p] = ffma2(a, w[p], acc[i][p]);
                }
            }
        }

        // ---- epilogue: h = relu(acc + Ps + Pr) -> bf16 hi/lo A images ----
        // ps/pr loads are coalesced: warp lanes span one row's 1024B contiguously
        #pragma unroll
        for (int i = 0; i < 4; i++) {
            int m = m0 + i;
            const float* ps = g_proj + (size_t)s_is[m] * PROJW + n0;
            const float* pr = g_proj + (size_t)s_ir[m] * PROJW + 256 + n0;
            float4 pa0 = *(const float4*)(ps);
            float4 pa1 = *(const float4*)(ps + 4);
            float4 pb0 = *(const float4*)(pr);
            float4 pb1 = *(const float4*)(pr + 4);
            float2 u0 = unpack2(acc[i][0]), u1 = unpack2(acc[i][1]);
            float2 u2 = unpack2(acc[i][2]), u3 = unpack2(acc[i][3]);
            float h0 = fmaxf(u0.x + pa0.x + pb0.x, 0.f);
            float h1 = fmaxf(u0.y + pa0.y + pb0.y, 0.f);
            float h2 = fmaxf(u1.x + pa0.z + pb0.z, 0.f);
            float h3 = fmaxf(u1.y + pa0.w + pb0.w, 0.f);
            float h4 = fmaxf(u2.x + pa1.x + pb1.x, 0.f);
            float h5 = fmaxf(u2.y + pa1.y + pb1.y, 0.f);
            float h6 = fmaxf(u3.x + pa1.z + pb1.z, 0.f);
            float h7 = fmaxf(u3.y + pa1.w + pb1.w, 0.f);

            u32 ph0 = pack_bf16x2(h0, h1), ph1 = pack_bf16x2(h2, h3);
            u32 ph2 = pack_bf16x2(h4, h5), ph3 = pack_bf16x2(h6, h7);
            u32 pl0 = pack_bf16x2(h0 - bf_lo_f(ph0), h1 - bf_hi_f(ph0));
            u32 pl1 = pack_bf16x2(h2 - bf_lo_f(ph1), h3 - bf_hi_f(ph1));
            u32 pl2 = pack_bf16x2(h4 - bf_lo_f(ph2), h5 - bf_hi_f(ph2));
            u32 pl3 = pack_bf16x2(h6 - bf_lo_f(ph3), h7 - bf_hi_f(ph3));

            u32 off = (u32)m * ASTB + (u32)(n0 * 2);
            *(uint4*)(smem + SM_AHI + off) = make_uint4(ph0, ph1, ph2, ph3);
            *(uint4*)(smem + SM_ALO + off) = make_uint4(pl0, pl1, pl2, pl3);
        }
        __syncthreads();

        // ---- GEMM2 via mma.sync bf16: D = Ah*Bh + Al*Bh + Ah*Bl ----
        float d[4][4];
        #pragma unroll
        for (int t = 0; t < 4; t++)
            #pragma unroll
            for (int j = 0; j < 4; j++) d[t][j] = 0.f;

        #pragma unroll 1
        for (int pass = 0; pass < 3; pass++) {
            u32 aB = (pass == 1) ? aOffLo : aOffHi;
            u32 bB = (pass == 2) ? bOffLo : bOffHi;
            #pragma unroll 4
            for (int k = 0; k < HID; k += 16) {
                u32 a0, a1, a2, a3;
                ldsm_x4(a0, a1, a2, a3, aB + (u32)(k * 2));
                u32 b0, b1, b2r, b3, b4, b5, b6, b7;
                ldsm_x4_t(b0, b1, b2r, b3, bB + (u32)(k * BSTB));
                ldsm_x4_t(b4, b5, b6, b7, bB + (u32)(k * BSTB) + 32);
                mma_bf16(d[0], a0, a1, a2, a3, b0, b1);
                mma_bf16(d[1], a0, a1, a2, a3, b2r, b3);
                mma_bf16(d[2], a0, a1, a2, a3, b4, b5);
                mma_bf16(d[3], a0, a1, a2, a3, b6, b7);
            }
        }

        // ---- epilogue: relu + gate partials + exp + scatter ----
        const int row1 = rw0 + group, row2 = row1 + 8;
        float v1[8], v2[8];
        float p1 = 0.f, p2 = 0.f;
        #pragma unroll
        for (int t = 0; t < 4; t++) {
            int c = cw0 + t * 8 + 2 * tg;
            float bb0 = s_b2[c], bb1 = s_b2[c + 1];
            float wg0 = s_wg[c], wg1 = s_wg[c + 1];
            float a0 = fmaxf(d[t][0] + bb0, 0.f), a1 = fmaxf(d[t][1] + bb1, 0.f);
            float a2 = fmaxf(d[t][2] + bb0, 0.f), a3 = fmaxf(d[t][3] + bb1, 0.f);
            v1[2 * t] = a0; v1[2 * t + 1] = a1;
            v2[2 * t] = a2; v2[2 * t + 1] = a3;
            p1 = fmaf(a0, wg0, fmaf(a1, wg1, p1));
            p2 = fmaf(a2, wg0, fmaf(a3, wg1, p2));
        }
        p1 += __shfl_xor_sync(0xffffffffu, p1, 1);
        p1 += __shfl_xor_sync(0xffffffffu, p1, 2);
        p2 += __shfl_xor_sync(0xffffffffu, p2, 1);
        p2 += __shfl_xor_sync(0xffffffffu, p2, 2);
        if (tg == 0) {
            s_gp[cg * 64 + row1] = p1;
            s_gp[cg * 64 + row2] = p2;
        }
        __syncthreads();

        if (e0 + row1 < cnt) {
            float tot = s_gp[row1] + s_gp[64 + row1] + s_gp[128 + row1] + s_gp[192 + row1];
            float ev = expf(tot + bg);
            int r = s_ir[row1];
            if (cg == 0 && tg == 0) atomicAdd(g_denom + r, ev);
            float* dst = g_aggr + (size_t)r * MSGD;
            #pragma unroll
            for (int t = 0; t < 4; t++)
                red_add_v2(dst + cw0 + t * 8 + 2 * tg, ev * v1[2 * t], ev * v1[2 * t + 1]);
        }
        if (e0 + row2 < cnt) {
            float tot = s_gp[row2] + s_gp[64 + row2] + s_gp[128 + row2] + s_gp[192 + row2];
            float ev = expf(tot + bg);
            int r = s_ir[row2];
            if (cg == 0 && tg == 0) atomicAdd(g_denom + r, ev);
            float* dst = g_aggr + (size_t)r * MSGD;
            #pragma unroll
            for (int t = 0; t < 4; t++)
                red_add_v2(dst + cw0 + t * 8 + 2 * tg, ev * v2[2 * t], ev * v2[2 * t + 1]);
        }
    }
}

// ---------------- agent MLP (divides by denom on load) -----------------------
__global__ __launch_bounds__(256, 2) void agent_mlp_kernel(
    const float* __restrict__ W_h1, const float* __restrict__ b_h1,
    const float* __restrict__ W_h2, const float* __restrict__ b_h2,
    const float* __restrict__ W_out, const float* __restrict__ b_out,
    float* __restrict__ out, int n_agents)
{
    extern __shared__ float smemf[];
    float (*s_x)[XPAD] = (float (*)[XPAD])smemf;
    float (*s_h)[HPAD] = (float (*)[HPAD])(smemf + BM * XPAD);

    const int r0 = blockIdx.x * BM;
    const int tid = threadIdx.x;

    for (int idx = tid; idx < BM * 32; idx += 256) {
        int m = idx >> 5, p = idx & 31;
        int r = r0 + m;
        float4 v = make_float4(0.f, 0.f, 0.f, 0.f);
        if (r < n_agents) {
            float inv = __frcp_rn(g_denom[r] + 1e-9f);
            v = *(const float4*)(g_aggr + (size_t)r * MSGD + p * 4);
            v.x *= inv; v.y *= inv; v.z *= inv; v.w *= inv;
        }
        *(float4*)&s_x[m][p * 4] = v;
    }
    __syncthreads();

    const int tx = tid & 31, ty = tid >> 5;
    const int n0 = tx * 8, m0 = ty * 8;

    u64 acc[8][4];
    {
        const u64* bp = (const u64*)(b_h1 + n0);
        u64 bv[4] = {bp[0], bp[1], bp[2], bp[3]};
        #pragma unroll
        for (int i = 0; i < 8; i++)
            #pragma unroll
            for (int p = 0; p < 4; p++) acc[i][p] = bv[p];
    }
    for (int k = 0; k < MSGD; k += 4) {
        float av[8][4];
        #pragma unroll
        for (int i = 0; i < 8; i++)
            *(float4*)av[i] = *(const float4*)&s_x[m0 + i][k];
        #pragma unroll
        for (int kk = 0; kk < 4; kk++) {
            const ulonglong2* wp = (const ulonglong2*)(W_h1 + (k + kk) * HID + n0);
            ulonglong2 w01 = wp[0], w23 = wp[1];
            u64 w[4] = {w01.x, w01.y, w23.x, w23.y};
            #pragma unroll
            for (int i = 0; i < 8; i++) {
                u64 a = pack2(av[i][kk]);
                #pragma unroll
                for (int p = 0; p < 4; p++) acc[i][p] = ffma2(a, w[p], acc[i][p]);
            }
        }
    }
    #pragma unroll
    for (int i = 0; i < 8; i++) {
        #pragma unroll
        for (int g = 0; g < 2; g++) {
            float2 u0 = unpack2(acc[i][2 * g]);
            float2 u1 = unpack2(acc[i][2 * g + 1]);
            float4 r;
            r.x = fmaxf(u0.x, 0.f); r.y = fmaxf(u0.y, 0.f);
            r.z = fmaxf(u1.x, 0.f); r.w = fmaxf(u1.y, 0.f);
            *(float4*)&s_h[m0 + i][n0 + g * 4] = r;
        }
    }
    __syncthreads();

    {
        const u64* bp = (const u64*)(b_h2 + n0);
        u64 bv[4] = {bp[0], bp[1], bp[2], bp[3]};
        #pragma unroll
        for (int i = 0; i < 8; i++)
            #pragma unroll
            for (int p = 0; p < 4; p++) acc[i][p] = bv[p];
    }
    #pragma unroll 2
    for (int k = 0; k < HID; k += 4) {
        float av[8][4];
        #pragma unroll
        for (int i = 0; i < 8; i++)
            *(float4*)av[i] = *(const float4*)&s_h[m0 + i][k];
        #pragma unroll
        for (int kk = 0; kk < 4; kk++) {
            const ulonglong2* wp = (const ulonglong2*)(W_h2 + (k + kk) * HID + n0);
            ulonglong2 w01 = wp[0], w23 = wp[1];
            u64 w[4] = {w01.x, w01.y, w23.x, w23.y};
            #pragma unroll
            for (int i = 0; i < 8; i++) {
                u64 a = pack2(av[i][kk]);
                #pragma unroll
                for (int p = 0; p < 4; p++) acc[i][p] = ffma2(a, w[p], acc[i][p]);
            }
        }
    }

    float wo[8];
    *(float4*)&wo[0] = *(const float4*)(W_out + n0);
    *(float4*)&wo[4] = *(const float4*)(W_out + n0 + 4);
    float partial[8];
    #pragma unroll
    for (int i = 0; i < 8; i++) {
        float s = 0.f;
        #pragma unroll
        for (int p = 0; p < 4; p++) {
            float2 u = unpack2(acc[i][p]);
            s = fmaf(fmaxf(u.x, 0.f), wo[2 * p], s);
            s = fmaf(fmaxf(u.y, 0.f), wo[2 * p + 1], s);
        }
        partial[i] = s;
    }
    #pragma unroll
    for (int o = 16; o >= 1; o >>= 1) {
        #pragma unroll
        for (int i = 0; i < 8; i++)
            partial[i] += __shfl_xor_sync(0xffffffffu, partial[i], o);
    }
    if (tx == 0) {
        float bo = b_out[0];
        #pragma unroll
        for (int i = 0; i < 8; i++) {
            int r = r0 + m0 + i;
            if (r < n_agents) out[r] = tanhf(partial[i] + bo);
        }
    }
}

// ---------------------------------------------------------------------------
extern "C" void kernel_launch(void* const* d_in, const int* in_sizes, int n_in,
                              void* d_out, int out_size) {
    const float* node_feats = (const float*)d_in[0];
    const float* edge_feats = (const float*)d_in[1];
    const float* W_msg1 = (const float*)d_in[2];
    const float* b_msg1 = (const float*)d_in[3];
    const float* W_msg2 = (const float*)d_in[4];
    const float* b_msg2 = (const float*)d_in[5];
    const float* w_gate = (const float*)d_in[6];
    const float* b_gate = (const float*)d_in[7];
    const float* W_h1   = (const float*)d_in[8];
    const float* b_h1   = (const float*)d_in[9];
    const float* W_h2   = (const float*)d_in[10];
    const float* b_h2   = (const float*)d_in[11];
    const float* W_out  = (const float*)d_in[12];
    const float* b_out  = (const float*)d_in[13];
    const int* senders   = (const int*)d_in[14];
    const int* receivers = (const int*)d_in[15];
    float* out = (float*)d_out;

    const int n_edges  = in_sizes[14];
    const int n_nodes  = in_sizes[0] / ND;
    const int n_agents = out_size;

    const int SMEM_AGENT = (BM * XPAD + BM * HPAD) * (int)sizeof(float);
    cudaFuncSetAttribute(edge_mlp_kernel, cudaFuncAttributeMaxDynamicSharedMemorySize, SM_TOT);
    cudaFuncSetAttribute(agent_mlp_kernel, cudaFuncAttributeMaxDynamicSharedMemorySize, SMEM_AGENT);

    {
        int total = n_agents * MSGD;
        init_kernel<<<(total + 255) / 256, 256>>>(n_agents);
    }
    w2_img_kernel<<<(HID * MSGD + 255) / 256, 256>>>(W_msg2);
    compact_kernel<<<(n_edges + 255) / 256, 256>>>(receivers, n_edges, n_agents);
    {
        dim3 grid((n_nodes + BM - 1) / BM, 2);
        node_proj_kernel<<<grid, 256>>>(node_feats, W_msg1, n_nodes, n_agents);
    }
    edge_mlp_kernel<<<148, 512, SM_TOT>>>(
        edge_feats, W_msg1, b_msg1, b_msg2, w_gate, b_gate, senders);
    agent_mlp_kernel<<<(n_agents + BM - 1) / BM, 256, SMEM_AGENT>>>(
        W_h1, b_h1, W_h2, b_h2, W_out, b_out, out, n_agents);
}